// round 4
// baseline (speedup 1.0000x reference)
#include <cuda_runtime.h>

#define BATCH 32
#define CH    512
#define HH    64
#define WW    64
#define KSEL  256           // RATIO 0.5 * 512
#define PLANE (HH * WW)     // 4096

// Scratch (allocation-free rule: __device__ globals)
__device__ float g_scores[BATCH * CH];
__device__ int   g_idx[BATCH * KSEL];

// ---------------------------------------------------------------------------
// Kernel 1: per-(b,c) plane curvature score = sum |valid 3x3 xcorr response|
// ONE WARP per plane, straight from global memory (no smem, no syncthreads):
//  - lane l loads float2 at cols (2l, 2l+1) of each input row (LDG.64; each
//    plane byte is fetched exactly once chip-wide)
//  - +2/+3 column neighbors via __shfl_down(1); rows slide through registers
//  - NUMERICS (R3 post-mortem): fp32 only within one row-pair
//    (|conv0|+|conv1| = single FADD with abs modifiers), then exact fp64
//    accumulation per thread + fp64 warp shuffle-tree. Score error ~1e-5 abs,
//    ~20x tighter than the R2 configuration that matched lax.top_k exactly.
// ---------------------------------------------------------------------------
__global__ __launch_bounds__(256) void score_kernel(const float* __restrict__ x,
                                                    const float* __restrict__ wgt) {
    const int lane  = threadIdx.x & 31;
    const int warp  = threadIdx.x >> 5;
    const int plane = blockIdx.x * 8 + warp;

    const float w0 = __ldg(wgt + 0), w1 = __ldg(wgt + 1), w2 = __ldg(wgt + 2);
    const float w3 = __ldg(wgt + 3), w4 = __ldg(wgt + 4), w5 = __ldg(wgt + 5);
    const float w6 = __ldg(wgt + 6), w7 = __ldg(wgt + 7), w8 = __ldg(wgt + 8);

    const float* base = x + (size_t)plane * PLANE + 2 * lane;
    const unsigned FULL = 0xffffffffu;

    float2 a = *reinterpret_cast<const float2*>(base);
    float2 b = *reinterpret_cast<const float2*>(base + WW);
    float anx = __shfl_down_sync(FULL, a.x, 1);
    float any = __shfl_down_sync(FULL, a.y, 1);
    float bnx = __shfl_down_sync(FULL, b.x, 1);
    float bny = __shfl_down_sync(FULL, b.y, 1);

    double acc = 0.0;
    #pragma unroll 2
    for (int i = 0; i < HH - 2; ++i) {
        const float2 c = *reinterpret_cast<const float2*>(base + (i + 2) * WW);
        const float cnx = __shfl_down_sync(FULL, c.x, 1);
        const float cny = __shfl_down_sync(FULL, c.y, 1);

        if (lane < 31) {   // lane 31 (cols 62/63) only feeds the shuffles
            // output col 2l: inputs cols 2l..2l+2, rows i..i+2
            float conv0 = w0 * a.x;
            conv0 = fmaf(w1, a.y, conv0);
            conv0 = fmaf(w2, anx, conv0);
            conv0 = fmaf(w3, b.x, conv0);
            conv0 = fmaf(w4, b.y, conv0);
            conv0 = fmaf(w5, bnx, conv0);
            conv0 = fmaf(w6, c.x, conv0);
            conv0 = fmaf(w7, c.y, conv0);
            conv0 = fmaf(w8, cnx, conv0);
            // output col 2l+1: inputs cols 2l+1..2l+3
            float conv1 = w0 * a.y;
            conv1 = fmaf(w1, anx, conv1);
            conv1 = fmaf(w2, any, conv1);
            conv1 = fmaf(w3, b.y, conv1);
            conv1 = fmaf(w4, bnx, conv1);
            conv1 = fmaf(w5, bny, conv1);
            conv1 = fmaf(w6, c.y, conv1);
            conv1 = fmaf(w7, cnx, conv1);
            conv1 = fmaf(w8, cny, conv1);
            const float rowsum = fabsf(conv0) + fabsf(conv1);  // 1 FADD w/ |.| mods
            acc += (double)rowsum;                             // exact fp64 chain
        }
        a = b;  anx = bnx;  any = bny;
        b = c;  bnx = cnx;  bny = cny;
    }

    // fp64 warp shuffle-tree reduction (exact up to fp64)
    #pragma unroll
    for (int off = 16; off > 0; off >>= 1)
        acc += __shfl_xor_sync(FULL, acc, off);
    if (lane == 0) g_scores[plane] = (float)acc;
}

// ---------------------------------------------------------------------------
// Kernel 2: per-batch top-k (k=256) via exact rank counting.
// rank = #(score strictly greater) + #(equal score with lower channel index),
// which reproduces lax.top_k ordering (descending value, ties -> lower index).
// ---------------------------------------------------------------------------
__global__ __launch_bounds__(512) void topk_kernel() {
    __shared__ float s[CH];
    const int b   = blockIdx.x;
    const int tid = threadIdx.x;

    s[tid] = g_scores[b * CH + tid];
    __syncthreads();

    const float my = s[tid];
    int rank = 0;
    #pragma unroll 8
    for (int j = 0; j < CH; ++j) {
        const float v = s[j];
        rank += (v > my) || (v == my && j < tid);
    }
    if (rank < KSEL) g_idx[b * KSEL + rank] = tid;
}

// ---------------------------------------------------------------------------
// Kernel 3: gather selected channel planes (contiguous 16KB float4 copies).
// ---------------------------------------------------------------------------
__global__ __launch_bounds__(256) void gather_kernel(const float* __restrict__ x,
                                                     float* __restrict__ out) {
    const int b = blockIdx.y;
    const int r = blockIdx.x;
    const int c = g_idx[b * KSEL + r];   // broadcast

    const float4* src = reinterpret_cast<const float4*>(x)
                        + ((size_t)(b * CH + c)) * (PLANE / 4);
    float4* dst = reinterpret_cast<float4*>(out)
                  + ((size_t)(b * KSEL + r)) * (PLANE / 4);
    #pragma unroll
    for (int i = threadIdx.x; i < PLANE / 4; i += 256) dst[i] = src[i];
}

extern "C" void kernel_launch(void* const* d_in, const int* in_sizes, int n_in,
                              void* d_out, int out_size) {
    const float* x = (const float*)d_in[0];
    const float* w = (const float*)d_in[1];
    // Defensive: metadata order should be (x, weight); swap if sizes say otherwise.
    if (n_in >= 2 && in_sizes[0] == 9) {
        const float* t = x; x = w; w = t;
    }
    float* out = (float*)d_out;

    score_kernel<<<(BATCH * CH) / 8, 256>>>(x, w);
    topk_kernel<<<BATCH, 512>>>();
    gather_kernel<<<dim3(KSEL, BATCH), 256>>>(x, out);
}

// round 5
// speedup vs baseline: 1.4931x; 1.4931x over previous
#include <cuda_runtime.h>

#define BATCH 32
#define CH    512
#define HH    64
#define WW    64
#define KSEL  256           // RATIO 0.5 * 512
#define PLANE (HH * WW)     // 4096

// Scratch (allocation-free rule: __device__ globals)
__device__ float g_scores[BATCH * CH];
__device__ int   g_idx[BATCH * KSEL];

// ---------------------------------------------------------------------------
// Kernel 1: per-(b,c) plane curvature score = sum |valid 3x3 xcorr response|
// ONE WARP per plane, straight from global memory (no smem, no syncthreads):
//  - lane l loads float2 at cols (2l, 2l+1) of each input row (LDG.64; each
//    plane byte is fetched exactly once chip-wide)
//  - +2/+3 column neighbors via __shfl_down(1); rows slide through registers
//  - NUMERICS (R3+R4 post-mortems): in-loop fp64 is latency/pipe-bound on
//    sm_103a, and a 124-term naive fp32 chain flips top-k ranks. Use fp32
//    KAHAN summation in the loop (error ~2eps*sum ~ 1e-5 abs, tighter than
//    the R2 config that matched lax.top_k exactly), fp64 only in the final
//    warp reduce. __fadd_rn keeps the compensation un-reassociable.
// ---------------------------------------------------------------------------
__global__ __launch_bounds__(256) void score_kernel(const float* __restrict__ x,
                                                    const float* __restrict__ wgt) {
    const int lane  = threadIdx.x & 31;
    const int warp  = threadIdx.x >> 5;
    const int plane = blockIdx.x * 8 + warp;

    const float w0 = __ldg(wgt + 0), w1 = __ldg(wgt + 1), w2 = __ldg(wgt + 2);
    const float w3 = __ldg(wgt + 3), w4 = __ldg(wgt + 4), w5 = __ldg(wgt + 5);
    const float w6 = __ldg(wgt + 6), w7 = __ldg(wgt + 7), w8 = __ldg(wgt + 8);

    const float* base = x + (size_t)plane * PLANE + 2 * lane;
    const unsigned FULL = 0xffffffffu;

    float2 a = *reinterpret_cast<const float2*>(base);
    float2 b = *reinterpret_cast<const float2*>(base + WW);
    float anx = __shfl_down_sync(FULL, a.x, 1);
    float any = __shfl_down_sync(FULL, a.y, 1);
    float bnx = __shfl_down_sync(FULL, b.x, 1);
    float bny = __shfl_down_sync(FULL, b.y, 1);

    float sum  = 0.0f;   // Kahan accumulator
    float comp = 0.0f;   // Kahan compensation
    #pragma unroll 2
    for (int i = 0; i < HH - 2; ++i) {
        const float2 c = *reinterpret_cast<const float2*>(base + (i + 2) * WW);
        const float cnx = __shfl_down_sync(FULL, c.x, 1);
        const float cny = __shfl_down_sync(FULL, c.y, 1);

        if (lane < 31) {   // lane 31 (cols 62/63) only feeds the shuffles
            // output col 2l: inputs cols 2l..2l+2, rows i..i+2
            float conv0 = w0 * a.x;
            conv0 = fmaf(w1, a.y, conv0);
            conv0 = fmaf(w2, anx, conv0);
            conv0 = fmaf(w3, b.x, conv0);
            conv0 = fmaf(w4, b.y, conv0);
            conv0 = fmaf(w5, bnx, conv0);
            conv0 = fmaf(w6, c.x, conv0);
            conv0 = fmaf(w7, c.y, conv0);
            conv0 = fmaf(w8, cnx, conv0);
            // output col 2l+1: inputs cols 2l+1..2l+3
            float conv1 = w0 * a.y;
            conv1 = fmaf(w1, anx, conv1);
            conv1 = fmaf(w2, any, conv1);
            conv1 = fmaf(w3, b.y, conv1);
            conv1 = fmaf(w4, bnx, conv1);
            conv1 = fmaf(w5, bny, conv1);
            conv1 = fmaf(w6, c.y, conv1);
            conv1 = fmaf(w7, cnx, conv1);
            conv1 = fmaf(w8, cny, conv1);
            const float rowsum = fabsf(conv0) + fabsf(conv1);
            // Kahan: sum += rowsum, carrying the lost low-order bits in comp
            const float y = __fadd_rn(rowsum, -comp);
            const float t = __fadd_rn(sum, y);
            comp = __fadd_rn(__fadd_rn(t, -sum), -y);
            sum = t;
        }
        a = b;  anx = bnx;  any = bny;
        b = c;  bnx = cnx;  bny = cny;
    }

    // fp64 warp shuffle-tree reduction (exact; outside the hot loop)
    double acc = (double)sum - (double)comp;
    #pragma unroll
    for (int off = 16; off > 0; off >>= 1)
        acc += __shfl_xor_sync(FULL, acc, off);
    if (lane == 0) g_scores[plane] = (float)acc;
}

// ---------------------------------------------------------------------------
// Kernel 2: per-batch top-k (k=256) via exact rank counting.
// rank = #(score strictly greater) + #(equal score with lower channel index),
// which reproduces lax.top_k ordering (descending value, ties -> lower index).
// ---------------------------------------------------------------------------
__global__ __launch_bounds__(512) void topk_kernel() {
    __shared__ float s[CH];
    const int b   = blockIdx.x;
    const int tid = threadIdx.x;

    s[tid] = g_scores[b * CH + tid];
    __syncthreads();

    const float my = s[tid];
    int rank = 0;
    #pragma unroll 8
    for (int j = 0; j < CH; ++j) {
        const float v = s[j];
        rank += (v > my) || (v == my && j < tid);
    }
    if (rank < KSEL) g_idx[b * KSEL + rank] = tid;
}

// ---------------------------------------------------------------------------
// Kernel 3: gather selected channel planes (contiguous 16KB float4 copies).
// ---------------------------------------------------------------------------
__global__ __launch_bounds__(256) void gather_kernel(const float* __restrict__ x,
                                                     float* __restrict__ out) {
    const int b = blockIdx.y;
    const int r = blockIdx.x;
    const int c = g_idx[b * KSEL + r];   // broadcast

    const float4* src = reinterpret_cast<const float4*>(x)
                        + ((size_t)(b * CH + c)) * (PLANE / 4);
    float4* dst = reinterpret_cast<float4*>(out)
                  + ((size_t)(b * KSEL + r)) * (PLANE / 4);
    #pragma unroll
    for (int i = threadIdx.x; i < PLANE / 4; i += 256) dst[i] = src[i];
}

extern "C" void kernel_launch(void* const* d_in, const int* in_sizes, int n_in,
                              void* d_out, int out_size) {
    const float* x = (const float*)d_in[0];
    const float* w = (const float*)d_in[1];
    // Defensive: metadata order should be (x, weight); swap if sizes say otherwise.
    if (n_in >= 2 && in_sizes[0] == 9) {
        const float* t = x; x = w; w = t;
    }
    float* out = (float*)d_out;

    score_kernel<<<(BATCH * CH) / 8, 256>>>(x, w);
    topk_kernel<<<BATCH, 512>>>();
    gather_kernel<<<dim3(KSEL, BATCH), 256>>>(x, out);
}

// round 6
// speedup vs baseline: 1.5797x; 1.0580x over previous
#include <cuda_runtime.h>

#define BATCH 32
#define CH    512
#define HH    64
#define WW    64
#define KSEL  256           // RATIO 0.5 * 512
#define PLANE (HH * WW)     // 4096

// Scratch (allocation-free rule: __device__ globals)
__device__ float g_scores[BATCH * CH];
__device__ int   g_idx[BATCH * KSEL];

// ---------------------------------------------------------------------------
// Kernel 1: per-(b,c) plane curvature score = sum |valid 3x3 xcorr response|
// ONE WARP per plane, straight from global memory (no smem, no syncthreads):
//  - lane l loads float2 at cols (2l, 2l+1) of each input row (LDG.64; each
//    plane byte is fetched exactly once chip-wide)
//  - R6: 4-deep register PREFETCH QUEUE (consume row i+2, load row i+6,
//    clamped) -> per-warp MLP ~4-6 instead of ~2; R5 was Little's-law bound
//    at 45% DRAM with only ~2 loads in flight per warp.
//  - +2/+3 column neighbors via __shfl_down(1); rows slide through registers
//  - NUMERICS (R3/R4 post-mortems): fp32 Kahan summation in the loop
//    (error ~1e-5 abs), fp64 only in the final warp shuffle reduce. This
//    exact configuration passed R5 with rel_err 0.0.
// ---------------------------------------------------------------------------
__global__ __launch_bounds__(256) void score_kernel(const float* __restrict__ x,
                                                    const float* __restrict__ wgt) {
    const int lane  = threadIdx.x & 31;
    const int warp  = threadIdx.x >> 5;
    const int plane = blockIdx.x * 8 + warp;

    const float w0 = __ldg(wgt + 0), w1 = __ldg(wgt + 1), w2 = __ldg(wgt + 2);
    const float w3 = __ldg(wgt + 3), w4 = __ldg(wgt + 4), w5 = __ldg(wgt + 5);
    const float w6 = __ldg(wgt + 6), w7 = __ldg(wgt + 7), w8 = __ldg(wgt + 8);

    // float2 view: row r of this plane at b2[r*32 + lane]
    const float2* b2 = reinterpret_cast<const float2*>(x)
                       + (size_t)plane * (PLANE / 2) + lane;
    const unsigned FULL = 0xffffffffu;

    // rows 0,1 (sliding window) + prefetch queue holding rows 2..5
    float2 a  = b2[0 * 32];
    float2 b  = b2[1 * 32];
    float2 q0 = b2[2 * 32];
    float2 q1 = b2[3 * 32];
    float2 q2 = b2[4 * 32];
    float2 q3 = b2[5 * 32];

    float anx = __shfl_down_sync(FULL, a.x, 1);
    float any = __shfl_down_sync(FULL, a.y, 1);
    float bnx = __shfl_down_sync(FULL, b.x, 1);
    float bny = __shfl_down_sync(FULL, b.y, 1);

    float sum  = 0.0f;   // Kahan accumulator
    float comp = 0.0f;   // Kahan compensation
    #pragma unroll 2
    for (int i = 0; i < HH - 2; ++i) {
        // consume row i+2 (loaded 4 iterations ago), refill with row i+6
        const float2 c = q0;
        q0 = q1; q1 = q2; q2 = q3;
        const int nr = (i + 6 < HH) ? (i + 6) : (HH - 1);  // clamp; tail data unused
        q3 = b2[nr * 32];

        const float cnx = __shfl_down_sync(FULL, c.x, 1);
        const float cny = __shfl_down_sync(FULL, c.y, 1);

        if (lane < 31) {   // lane 31 (cols 62/63) only feeds the shuffles
            // output col 2l: inputs cols 2l..2l+2, rows i..i+2
            float conv0 = w0 * a.x;
            conv0 = fmaf(w1, a.y, conv0);
            conv0 = fmaf(w2, anx, conv0);
            conv0 = fmaf(w3, b.x, conv0);
            conv0 = fmaf(w4, b.y, conv0);
            conv0 = fmaf(w5, bnx, conv0);
            conv0 = fmaf(w6, c.x, conv0);
            conv0 = fmaf(w7, c.y, conv0);
            conv0 = fmaf(w8, cnx, conv0);
            // output col 2l+1: inputs cols 2l+1..2l+3
            float conv1 = w0 * a.y;
            conv1 = fmaf(w1, anx, conv1);
            conv1 = fmaf(w2, any, conv1);
            conv1 = fmaf(w3, b.y, conv1);
            conv1 = fmaf(w4, bnx, conv1);
            conv1 = fmaf(w5, bny, conv1);
            conv1 = fmaf(w6, c.y, conv1);
            conv1 = fmaf(w7, cnx, conv1);
            conv1 = fmaf(w8, cny, conv1);
            const float rowsum = fabsf(conv0) + fabsf(conv1);
            // Kahan: sum += rowsum, carrying the lost low-order bits in comp
            const float y = __fadd_rn(rowsum, -comp);
            const float t = __fadd_rn(sum, y);
            comp = __fadd_rn(__fadd_rn(t, -sum), -y);
            sum = t;
        }
        a = b;  anx = bnx;  any = bny;
        b = c;  bnx = cnx;  bny = cny;
    }

    // fp64 warp shuffle-tree reduction (exact; outside the hot loop)
    double acc = (double)sum - (double)comp;
    #pragma unroll
    for (int off = 16; off > 0; off >>= 1)
        acc += __shfl_xor_sync(FULL, acc, off);
    if (lane == 0) g_scores[plane] = (float)acc;
}

// ---------------------------------------------------------------------------
// Kernel 2: per-batch top-k (k=256) via exact rank counting.
// rank = #(score strictly greater) + #(equal score with lower channel index),
// which reproduces lax.top_k ordering (descending value, ties -> lower index).
// ---------------------------------------------------------------------------
__global__ __launch_bounds__(512) void topk_kernel() {
    __shared__ float s[CH];
    const int b   = blockIdx.x;
    const int tid = threadIdx.x;

    s[tid] = g_scores[b * CH + tid];
    __syncthreads();

    const float my = s[tid];
    int rank = 0;
    #pragma unroll 8
    for (int j = 0; j < CH; ++j) {
        const float v = s[j];
        rank += (v > my) || (v == my && j < tid);
    }
    if (rank < KSEL) g_idx[b * KSEL + rank] = tid;
}

// ---------------------------------------------------------------------------
// Kernel 3: gather selected channel planes (contiguous 16KB float4 copies).
// ---------------------------------------------------------------------------
__global__ __launch_bounds__(256) void gather_kernel(const float* __restrict__ x,
                                                     float* __restrict__ out) {
    const int b = blockIdx.y;
    const int r = blockIdx.x;
    const int c = g_idx[b * KSEL + r];   // broadcast

    const float4* src = reinterpret_cast<const float4*>(x)
                        + ((size_t)(b * CH + c)) * (PLANE / 4);
    float4* dst = reinterpret_cast<float4*>(out)
                  + ((size_t)(b * KSEL + r)) * (PLANE / 4);
    #pragma unroll
    for (int i = threadIdx.x; i < PLANE / 4; i += 256) dst[i] = src[i];
}

extern "C" void kernel_launch(void* const* d_in, const int* in_sizes, int n_in,
                              void* d_out, int out_size) {
    const float* x = (const float*)d_in[0];
    const float* w = (const float*)d_in[1];
    // Defensive: metadata order should be (x, weight); swap if sizes say otherwise.
    if (n_in >= 2 && in_sizes[0] == 9) {
        const float* t = x; x = w; w = t;
    }
    float* out = (float*)d_out;

    score_kernel<<<(BATCH * CH) / 8, 256>>>(x, w);
    topk_kernel<<<BATCH, 512>>>();
    gather_kernel<<<dim3(KSEL, BATCH), 256>>>(x, out);
}

// round 7
// speedup vs baseline: 1.7579x; 1.1128x over previous
#include <cuda_runtime.h>

#define BATCH 32
#define CH    512
#define HH    64
#define WW    64
#define KSEL  256           // RATIO 0.5 * 512
#define PLANE (HH * WW)     // 4096

// Scratch (allocation-free rule: __device__ globals)
__device__ float g_scores[BATCH * CH];
__device__ int   g_idx[BATCH * KSEL];

// ---------------------------------------------------------------------------
// Kernel 1: per-(b,c) plane curvature score = sum |valid 3x3 xcorr response|
// ONE WARP per plane, straight from global memory (no smem, no syncthreads):
//  - lane l loads float2 at cols (2l, 2l+1) of each input row (LDG.64; each
//    plane byte is fetched exactly once chip-wide)
//  - 4-deep register prefetch queue (consume row i+2, load row i+6 clamped)
//  - R7: unroll 8 + statically-indexed queue q[i&3] -> rotation MOVs become
//    register renaming; 128-thr blocks with __launch_bounds__(128,12) to cap
//    regs and restore ~75% occupancy (R6 was alu/issue-bound at occ 59%).
//  - +2/+3 column neighbors via __shfl_down(1); rows slide through registers
//  - NUMERICS: unchanged from the R5/R6 passing config — fp32 Kahan in-loop,
//    fp64 only in the final warp shuffle reduce.
// ---------------------------------------------------------------------------
__global__ __launch_bounds__(128, 12) void score_kernel(const float* __restrict__ x,
                                                        const float* __restrict__ wgt) {
    const int lane  = threadIdx.x & 31;
    const int warp  = threadIdx.x >> 5;
    const int plane = blockIdx.x * 4 + warp;

    const float w0 = __ldg(wgt + 0), w1 = __ldg(wgt + 1), w2 = __ldg(wgt + 2);
    const float w3 = __ldg(wgt + 3), w4 = __ldg(wgt + 4), w5 = __ldg(wgt + 5);
    const float w6 = __ldg(wgt + 6), w7 = __ldg(wgt + 7), w8 = __ldg(wgt + 8);

    // float2 view: row r of this plane at b2[r*32 + lane]
    const float2* b2 = reinterpret_cast<const float2*>(x)
                       + (size_t)plane * (PLANE / 2) + lane;
    const unsigned FULL = 0xffffffffu;

    // rows 0,1 (sliding window) + prefetch queue holding rows 2..5
    float2 a = b2[0 * 32];
    float2 b = b2[1 * 32];
    float2 q[4];
    q[0] = b2[2 * 32];
    q[1] = b2[3 * 32];
    q[2] = b2[4 * 32];
    q[3] = b2[5 * 32];

    float anx = __shfl_down_sync(FULL, a.x, 1);
    float any = __shfl_down_sync(FULL, a.y, 1);
    float bnx = __shfl_down_sync(FULL, b.x, 1);
    float bny = __shfl_down_sync(FULL, b.y, 1);

    float sum  = 0.0f;   // Kahan accumulator
    float comp = 0.0f;   // Kahan compensation
    #pragma unroll 8
    for (int i = 0; i < HH - 2; ++i) {
        // consume row i+2 (loaded 4 iterations ago), refill slot with row i+6
        const float2 c = q[i & 3];
        const int nr = (i + 6 < HH) ? (i + 6) : (HH - 1);  // clamp; tail unused
        q[i & 3] = b2[nr * 32];

        const float cnx = __shfl_down_sync(FULL, c.x, 1);
        const float cny = __shfl_down_sync(FULL, c.y, 1);

        if (lane < 31) {   // lane 31 (cols 62/63) only feeds the shuffles
            // output col 2l: inputs cols 2l..2l+2, rows i..i+2
            float conv0 = w0 * a.x;
            conv0 = fmaf(w1, a.y, conv0);
            conv0 = fmaf(w2, anx, conv0);
            conv0 = fmaf(w3, b.x, conv0);
            conv0 = fmaf(w4, b.y, conv0);
            conv0 = fmaf(w5, bnx, conv0);
            conv0 = fmaf(w6, c.x, conv0);
            conv0 = fmaf(w7, c.y, conv0);
            conv0 = fmaf(w8, cnx, conv0);
            // output col 2l+1: inputs cols 2l+1..2l+3
            float conv1 = w0 * a.y;
            conv1 = fmaf(w1, anx, conv1);
            conv1 = fmaf(w2, any, conv1);
            conv1 = fmaf(w3, b.y, conv1);
            conv1 = fmaf(w4, bnx, conv1);
            conv1 = fmaf(w5, bny, conv1);
            conv1 = fmaf(w6, c.y, conv1);
            conv1 = fmaf(w7, cnx, conv1);
            conv1 = fmaf(w8, cny, conv1);
            const float rowsum = fabsf(conv0) + fabsf(conv1);
            // Kahan: sum += rowsum, carrying the lost low-order bits in comp
            const float y = __fadd_rn(rowsum, -comp);
            const float t = __fadd_rn(sum, y);
            comp = __fadd_rn(__fadd_rn(t, -sum), -y);
            sum = t;
        }
        a = b;  anx = bnx;  any = bny;
        b = c;  bnx = cnx;  bny = cny;
    }

    // fp64 warp shuffle-tree reduction (exact; outside the hot loop)
    double acc = (double)sum - (double)comp;
    #pragma unroll
    for (int off = 16; off > 0; off >>= 1)
        acc += __shfl_xor_sync(FULL, acc, off);
    if (lane == 0) g_scores[plane] = (float)acc;
}

// ---------------------------------------------------------------------------
// Kernel 2: per-batch top-k (k=256) via exact rank counting.
// rank = #(score strictly greater) + #(equal score with lower channel index),
// which reproduces lax.top_k ordering (descending value, ties -> lower index).
// ---------------------------------------------------------------------------
__global__ __launch_bounds__(512) void topk_kernel() {
    __shared__ float s[CH];
    const int b   = blockIdx.x;
    const int tid = threadIdx.x;

    s[tid] = g_scores[b * CH + tid];
    __syncthreads();

    const float my = s[tid];
    int rank = 0;
    #pragma unroll 8
    for (int j = 0; j < CH; ++j) {
        const float v = s[j];
        rank += (v > my) || (v == my && j < tid);
    }
    if (rank < KSEL) g_idx[b * KSEL + rank] = tid;
}

// ---------------------------------------------------------------------------
// Kernel 3: gather selected channel planes (contiguous 16KB float4 copies).
// ---------------------------------------------------------------------------
__global__ __launch_bounds__(256) void gather_kernel(const float* __restrict__ x,
                                                     float* __restrict__ out) {
    const int b = blockIdx.y;
    const int r = blockIdx.x;
    const int c = g_idx[b * KSEL + r];   // broadcast

    const float4* src = reinterpret_cast<const float4*>(x)
                        + ((size_t)(b * CH + c)) * (PLANE / 4);
    float4* dst = reinterpret_cast<float4*>(out)
                  + ((size_t)(b * KSEL + r)) * (PLANE / 4);
    #pragma unroll
    for (int i = threadIdx.x; i < PLANE / 4; i += 256) dst[i] = src[i];
}

extern "C" void kernel_launch(void* const* d_in, const int* in_sizes, int n_in,
                              void* d_out, int out_size) {
    const float* x = (const float*)d_in[0];
    const float* w = (const float*)d_in[1];
    // Defensive: metadata order should be (x, weight); swap if sizes say otherwise.
    if (n_in >= 2 && in_sizes[0] == 9) {
        const float* t = x; x = w; w = t;
    }
    float* out = (float*)d_out;

    score_kernel<<<(BATCH * CH) / 4, 128>>>(x, w);
    topk_kernel<<<BATCH, 512>>>();
    gather_kernel<<<dim3(KSEL, BATCH), 256>>>(x, out);
}

// round 8
// speedup vs baseline: 1.8279x; 1.0398x over previous
#include <cuda_runtime.h>

#define BATCH 32
#define CH    512
#define HH    64
#define WW    64
#define KSEL  256           // RATIO 0.5 * 512
#define PLANE (HH * WW)     // 4096

// Scratch (allocation-free rule: __device__ globals)
__device__ float g_scores[BATCH * CH];
__device__ int   g_idx[BATCH * KSEL];

// ---------------------------------------------------------------------------
// Kernel 1: per-(b,c) plane curvature score = sum |valid 3x3 xcorr response|
// ONE WARP per plane, straight from global (no smem):
//  - lane l loads float2 at cols (2l,2l+1) per row (LDG.64, each byte once)
//  - 4-deep register prefetch queue q[i&3], unroll 8 (R6/R7)
//  - R8: SYMMETRIC-STENCIL FACTORIZATION. The 3x3 kernel has 3 distinct
//    weights (corner wc, edge we, center w4):
//      conv = wc*(tA+tC) + we*(mA+mC+tB) + w4*mB,
//      tR = x[R][c]+x[R][c+2], mR = x[R][c+1]
//    Each row's t is computed once and reused by 3 output rows ->
//    18 fma-pipe ops/iter vs 22, and only 3 weight registers.
//  - NUMERICS: fp32 Kahan in-loop + fp64 final warp reduce (passing config;
//    the factorization is a few-ulp re-association, far below rank gaps).
// ---------------------------------------------------------------------------
__global__ __launch_bounds__(128, 12) void score_kernel(const float* __restrict__ x,
                                                        const float* __restrict__ wgt) {
    const int lane  = threadIdx.x & 31;
    const int warp  = threadIdx.x >> 5;
    const int plane = blockIdx.x * 4 + warp;

    const float wc = __ldg(wgt + 0);   // corners (-1/16)
    const float we = __ldg(wgt + 1);   // edges   ( 5/16)
    const float w4 = __ldg(wgt + 4);   // center  (-1)

    // float2 view: row r of this plane at b2[r*32 + lane]
    const float2* b2 = reinterpret_cast<const float2*>(x)
                       + (size_t)plane * (PLANE / 2) + lane;
    const unsigned FULL = 0xffffffffu;

    // Prefetch queue holds rows 2..5
    float2 q[4];
    {
        // prologue: rows 0,1 -> factored state; rows 2..5 -> queue
        const float2 r0 = b2[0 * 32];
        const float2 r1 = b2[1 * 32];
        q[0] = b2[2 * 32];
        q[1] = b2[3 * 32];
        q[2] = b2[4 * 32];
        q[3] = b2[5 * 32];

        const float r0nx = __shfl_down_sync(FULL, r0.x, 1);
        const float r0ny = __shfl_down_sync(FULL, r0.y, 1);
        const float r1nx = __shfl_down_sync(FULL, r1.x, 1);
        const float r1ny = __shfl_down_sync(FULL, r1.y, 1);

        // row state: t0/t1 = outer-pair sums for output cols 2l / 2l+1,
        //            m0/m1 = middle elements
        float tA0 = r0.x + r0nx, tA1 = r0.y + r0ny;
        float mA0 = r0.y,        mA1 = r0nx;
        float tB0 = r1.x + r1nx, tB1 = r1.y + r1ny;
        float mB0 = r1.y,        mB1 = r1nx;

        float sum  = 0.0f;   // Kahan accumulator
        float comp = 0.0f;   // Kahan compensation

        #pragma unroll 8
        for (int i = 0; i < HH - 2; ++i) {
            // consume row i+2 (loaded 4 iters ago), refill with row i+6
            const float2 c = q[i & 3];
            const int nr = (i + 6 < HH) ? (i + 6) : (HH - 1);  // clamp; tail unused
            q[i & 3] = b2[nr * 32];

            const float cnx = __shfl_down_sync(FULL, c.x, 1);
            const float cny = __shfl_down_sync(FULL, c.y, 1);

            const float tC0 = c.x + cnx, tC1 = c.y + cny;
            const float mC0 = c.y,       mC1 = cnx;

            if (lane < 31) {   // lane 31 (cols 62/63) only feeds the shuffles
                // output col 2l
                const float u0 = tA0 + tC0;
                float v0 = mA0 + mC0;
                v0 += tB0;
                float conv0 = wc * u0;
                conv0 = fmaf(we, v0, conv0);
                conv0 = fmaf(w4, mB0, conv0);
                // output col 2l+1
                const float u1 = tA1 + tC1;
                float v1 = mA1 + mC1;
                v1 += tB1;
                float conv1 = wc * u1;
                conv1 = fmaf(we, v1, conv1);
                conv1 = fmaf(w4, mB1, conv1);

                const float rowsum = fabsf(conv0) + fabsf(conv1);
                // Kahan: sum += rowsum
                const float y = __fadd_rn(rowsum, -comp);
                const float t = __fadd_rn(sum, y);
                comp = __fadd_rn(__fadd_rn(t, -sum), -y);
                sum = t;
            }
            // slide row states
            tA0 = tB0; tA1 = tB1; mA0 = mB0; mA1 = mB1;
            tB0 = tC0; tB1 = tC1; mB0 = mC0; mB1 = mC1;
        }

        // fp64 warp shuffle-tree reduction (exact; outside the hot loop)
        double acc = (double)sum - (double)comp;
        #pragma unroll
        for (int off = 16; off > 0; off >>= 1)
            acc += __shfl_xor_sync(FULL, acc, off);
        if (lane == 0) g_scores[plane] = (float)acc;
    }
}

// ---------------------------------------------------------------------------
// Kernel 2: per-batch top-k (k=256) via exact rank counting.
// rank = #(score strictly greater) + #(equal score with lower channel index),
// which reproduces lax.top_k ordering (descending value, ties -> lower index).
// ---------------------------------------------------------------------------
__global__ __launch_bounds__(512) void topk_kernel() {
    __shared__ float s[CH];
    const int b   = blockIdx.x;
    const int tid = threadIdx.x;

    s[tid] = g_scores[b * CH + tid];
    __syncthreads();

    const float my = s[tid];
    int rank = 0;
    #pragma unroll 8
    for (int j = 0; j < CH; ++j) {
        const float v = s[j];
        rank += (v > my) || (v == my && j < tid);
    }
    if (rank < KSEL) g_idx[b * KSEL + rank] = tid;
}

// ---------------------------------------------------------------------------
// Kernel 3: gather selected channel planes (contiguous 16KB float4 copies).
// ---------------------------------------------------------------------------
__global__ __launch_bounds__(256) void gather_kernel(const float* __restrict__ x,
                                                     float* __restrict__ out) {
    const int b = blockIdx.y;
    const int r = blockIdx.x;
    const int c = g_idx[b * KSEL + r];   // broadcast

    const float4* src = reinterpret_cast<const float4*>(x)
                        + ((size_t)(b * CH + c)) * (PLANE / 4);
    float4* dst = reinterpret_cast<float4*>(out)
                  + ((size_t)(b * KSEL + r)) * (PLANE / 4);
    #pragma unroll
    for (int i = threadIdx.x; i < PLANE / 4; i += 256) dst[i] = src[i];
}

extern "C" void kernel_launch(void* const* d_in, const int* in_sizes, int n_in,
                              void* d_out, int out_size) {
    const float* x = (const float*)d_in[0];
    const float* w = (const float*)d_in[1];
    // Defensive: metadata order should be (x, weight); swap if sizes say otherwise.
    if (n_in >= 2 && in_sizes[0] == 9) {
        const float* t = x; x = w; w = t;
    }
    float* out = (float*)d_out;

    score_kernel<<<(BATCH * CH) / 4, 128>>>(x, w);
    topk_kernel<<<BATCH, 512>>>();
    gather_kernel<<<dim3(KSEL, BATCH), 256>>>(x, out);
}

// round 10
// speedup vs baseline: 1.8546x; 1.0146x over previous
#include <cuda_runtime.h>

#define BATCH 32
#define CH    512
#define HH    64
#define WW    64
#define KSEL  256           // RATIO 0.5 * 512
#define PLANE (HH * WW)     // 4096

// Scratch (allocation-free rule: __device__ globals)
__device__ float g_scores[BATCH * CH];
__device__ int   g_idx[BATCH * KSEL];

// ---------------------------------------------------------------------------
// Kernel 1: per-(b,c) plane curvature score = sum |valid 3x3 xcorr response|
// ONE WARP per plane, straight from global (no smem):
//  - lane l loads float2 at cols (2l,2l+1) per row (LDG.64, each byte once)
//  - 4-deep register prefetch queue q[i&3], unroll 8
//  - symmetric-stencil factorization (3 distinct weights):
//      conv = wc*(tA+tC) + we*(mA+mC+tB) + w4*mB
//  - branchless lane handling: all 32 lanes compute (lane 31 gets finite
//    self-shuffle garbage), its Kahan state zeroed before the reduce.
//  - R10 FIX of R9 off-by-one: prefetch loop must run i<58 so rows 62,63
//    are loaded (queue lookahead is 4; last prefetch i=57 -> row 63).
//    Drain i=58..61 consumes rows 60..63. i+6<=63 in main loop -> no clamp.
//  - NUMERICS: fp32 Kahan in-loop + fp64 final warp reduce (passing config).
// ---------------------------------------------------------------------------
__global__ __launch_bounds__(128, 12) void score_kernel(const float* __restrict__ x,
                                                        const float* __restrict__ wgt) {
    const int lane  = threadIdx.x & 31;
    const int warp  = threadIdx.x >> 5;
    const int plane = blockIdx.x * 4 + warp;

    const float wc = __ldg(wgt + 0);   // corners (-1/16)
    const float we = __ldg(wgt + 1);   // edges   ( 5/16)
    const float w4 = __ldg(wgt + 4);   // center  (-1)

    // float2 view: row r of this plane at b2[r*32 + lane]
    const float2* b2 = reinterpret_cast<const float2*>(x)
                       + (size_t)plane * (PLANE / 2) + lane;
    const unsigned FULL = 0xffffffffu;

    // prologue: rows 0,1 -> factored state; rows 2..5 -> prefetch queue
    const float2 r0 = b2[0 * 32];
    const float2 r1 = b2[1 * 32];
    float2 q[4];
    q[0] = b2[2 * 32];
    q[1] = b2[3 * 32];
    q[2] = b2[4 * 32];
    q[3] = b2[5 * 32];

    const float r0nx = __shfl_down_sync(FULL, r0.x, 1);
    const float r0ny = __shfl_down_sync(FULL, r0.y, 1);
    const float r1nx = __shfl_down_sync(FULL, r1.x, 1);
    const float r1ny = __shfl_down_sync(FULL, r1.y, 1);

    // row state: t = outer-pair sums (cols 2l / 2l+1), m = middle elements
    float tA0 = r0.x + r0nx, tA1 = r0.y + r0ny;
    float mA0 = r0.y,        mA1 = r0nx;
    float tB0 = r1.x + r1nx, tB1 = r1.y + r1ny;
    float mB0 = r1.y,        mB1 = r1nx;

    float sum  = 0.0f;   // Kahan accumulator
    float comp = 0.0f;   // Kahan compensation

    // branchless body: every lane computes; lane 31 is zeroed before reduce
    auto body = [&](const float2 c) {
        const float cnx = __shfl_down_sync(FULL, c.x, 1);
        const float cny = __shfl_down_sync(FULL, c.y, 1);
        const float tC0 = c.x + cnx, tC1 = c.y + cny;
        const float mC0 = c.y,       mC1 = cnx;

        // output col 2l
        const float u0 = tA0 + tC0;
        float v0 = mA0 + mC0;
        v0 += tB0;
        float conv0 = wc * u0;
        conv0 = fmaf(we, v0, conv0);
        conv0 = fmaf(w4, mB0, conv0);
        // output col 2l+1
        const float u1 = tA1 + tC1;
        float v1 = mA1 + mC1;
        v1 += tB1;
        float conv1 = wc * u1;
        conv1 = fmaf(we, v1, conv1);
        conv1 = fmaf(w4, mB1, conv1);

        const float rowsum = fabsf(conv0) + fabsf(conv1);
        // Kahan: sum += rowsum
        const float y = __fadd_rn(rowsum, -comp);
        const float t = __fadd_rn(sum, y);
        comp = __fadd_rn(__fadd_rn(t, -sum), -y);
        sum = t;

        // slide row states
        tA0 = tB0; tA1 = tB1; mA0 = mB0; mA1 = mB1;
        tB0 = tC0; tB1 = tC1; mB0 = mC0; mB1 = mC1;
    };

    // main loop: prefetch rows 6..63 (i+6 <= 63 for i < 58 -> no clamp)
    #pragma unroll 8
    for (int i = 0; i < 58; ++i) {
        const float2 c = q[i & 3];
        q[i & 3] = b2[(i + 6) * 32];
        body(c);
    }
    // drain: consume rows 60..63 (stored at i=54..57), no more loads
    #pragma unroll
    for (int i = 58; i < HH - 2; ++i) {
        body(q[i & 3]);
    }

    // lane 31 (cols 62/63) only fed shuffles — drop its contribution
    if (lane == 31) { sum = 0.0f; comp = 0.0f; }

    // fp64 warp shuffle-tree reduction (exact; outside the hot loop)
    double acc = (double)sum - (double)comp;
    #pragma unroll
    for (int off = 16; off > 0; off >>= 1)
        acc += __shfl_xor_sync(FULL, acc, off);
    if (lane == 0) g_scores[plane] = (float)acc;
}

// ---------------------------------------------------------------------------
// Kernel 2: per-batch top-k (k=256) via exact rank counting.
// rank = #(score strictly greater) + #(equal score with lower channel index),
// which reproduces lax.top_k ordering (descending value, ties -> lower index).
// ---------------------------------------------------------------------------
__global__ __launch_bounds__(512) void topk_kernel() {
    __shared__ float s[CH];
    const int b   = blockIdx.x;
    const int tid = threadIdx.x;

    s[tid] = g_scores[b * CH + tid];
    __syncthreads();

    const float my = s[tid];
    int rank = 0;
    #pragma unroll 8
    for (int j = 0; j < CH; ++j) {
        const float v = s[j];
        rank += (v > my) || (v == my && j < tid);
    }
    if (rank < KSEL) g_idx[b * KSEL + rank] = tid;
}

// ---------------------------------------------------------------------------
// Kernel 3: gather selected channel planes (contiguous 16KB float4 copies).
// ---------------------------------------------------------------------------
__global__ __launch_bounds__(256) void gather_kernel(const float* __restrict__ x,
                                                     float* __restrict__ out) {
    const int b = blockIdx.y;
    const int r = blockIdx.x;
    const int c = g_idx[b * KSEL + r];   // broadcast

    const float4* src = reinterpret_cast<const float4*>(x)
                        + ((size_t)(b * CH + c)) * (PLANE / 4);
    float4* dst = reinterpret_cast<float4*>(out)
                  + ((size_t)(b * KSEL + r)) * (PLANE / 4);
    #pragma unroll
    for (int i = threadIdx.x; i < PLANE / 4; i += 256) dst[i] = src[i];
}

extern "C" void kernel_launch(void* const* d_in, const int* in_sizes, int n_in,
                              void* d_out, int out_size) {
    const float* x = (const float*)d_in[0];
    const float* w = (const float*)d_in[1];
    // Defensive: metadata order should be (x, weight); swap if sizes say otherwise.
    if (n_in >= 2 && in_sizes[0] == 9) {
        const float* t = x; x = w; w = t;
    }
    float* out = (float*)d_out;

    score_kernel<<<(BATCH * CH) / 4, 128>>>(x, w);
    topk_kernel<<<BATCH, 512>>>();
    gather_kernel<<<dim3(KSEL, BATCH), 256>>>(x, out);
}

// round 11
// speedup vs baseline: 1.8797x; 1.0135x over previous
#include <cuda_runtime.h>

#define BATCH 32
#define CH    512
#define HH    64
#define WW    64
#define KSEL  256           // RATIO 0.5 * 512
#define PLANE (HH * WW)     // 4096

// Scratch (allocation-free rule: __device__ globals)
__device__ float g_scores[BATCH * CH];
__device__ int   g_idx[BATCH * KSEL];

// ---------------------------------------------------------------------------
// Kernel 1: per-(b,c) plane curvature score = sum |valid 3x3 xcorr response|
// ONE WARP per plane, straight from global (no smem):
//  - lane l loads float2 at cols (2l,2l+1) per row (LDG.64, each byte once)
//  - R11: 8-deep register prefetch queue q[i&7] (consume row i+2, load row
//    i+10) -> ~2KB in flight per warp; R10 was still latency-bound at
//    DRAM=73% with depth 4. Occupancy cost (48->40 warps) is paid for by 2x
//    in-flight bytes/SM.
//  - symmetric-stencil factorization (3 distinct weights):
//      conv = wc*(tA+tC) + we*(mA+mC+tB) + w4*mB
//  - branchless: all 32 lanes compute; lane 31's Kahan state zeroed pre-reduce.
//  - loop split: prefetch i<54 (last load i=53 -> row 63; i+10<=63 so no
//    clamp), drain i=54..61 consumes rows 56..63.
//  - NUMERICS: fp32 Kahan in-loop + fp64 final warp reduce (passing config).
// ---------------------------------------------------------------------------
__global__ __launch_bounds__(128, 10) void score_kernel(const float* __restrict__ x,
                                                         const float* __restrict__ wgt) {
    const int lane  = threadIdx.x & 31;
    const int warp  = threadIdx.x >> 5;
    const int plane = blockIdx.x * 4 + warp;

    const float wc = __ldg(wgt + 0);   // corners (-1/16)
    const float we = __ldg(wgt + 1);   // edges   ( 5/16)
    const float w4 = __ldg(wgt + 4);   // center  (-1)

    // float2 view: row r of this plane at b2[r*32 + lane]
    const float2* b2 = reinterpret_cast<const float2*>(x)
                       + (size_t)plane * (PLANE / 2) + lane;
    const unsigned FULL = 0xffffffffu;

    // prologue: rows 0,1 -> factored state; rows 2..9 -> prefetch queue
    const float2 r0 = b2[0 * 32];
    const float2 r1 = b2[1 * 32];
    float2 q[8];
    #pragma unroll
    for (int j = 0; j < 8; ++j) q[j] = b2[(j + 2) * 32];

    const float r0nx = __shfl_down_sync(FULL, r0.x, 1);
    const float r0ny = __shfl_down_sync(FULL, r0.y, 1);
    const float r1nx = __shfl_down_sync(FULL, r1.x, 1);
    const float r1ny = __shfl_down_sync(FULL, r1.y, 1);

    // row state: t = outer-pair sums (cols 2l / 2l+1), m = middle elements
    float tA0 = r0.x + r0nx, tA1 = r0.y + r0ny;
    float mA0 = r0.y,        mA1 = r0nx;
    float tB0 = r1.x + r1nx, tB1 = r1.y + r1ny;
    float mB0 = r1.y,        mB1 = r1nx;

    float sum  = 0.0f;   // Kahan accumulator
    float comp = 0.0f;   // Kahan compensation

    // branchless body: every lane computes; lane 31 is zeroed before reduce
    auto body = [&](const float2 c) {
        const float cnx = __shfl_down_sync(FULL, c.x, 1);
        const float cny = __shfl_down_sync(FULL, c.y, 1);
        const float tC0 = c.x + cnx, tC1 = c.y + cny;
        const float mC0 = c.y,       mC1 = cnx;

        // output col 2l
        const float u0 = tA0 + tC0;
        float v0 = mA0 + mC0;
        v0 += tB0;
        float conv0 = wc * u0;
        conv0 = fmaf(we, v0, conv0);
        conv0 = fmaf(w4, mB0, conv0);
        // output col 2l+1
        const float u1 = tA1 + tC1;
        float v1 = mA1 + mC1;
        v1 += tB1;
        float conv1 = wc * u1;
        conv1 = fmaf(we, v1, conv1);
        conv1 = fmaf(w4, mB1, conv1);

        const float rowsum = fabsf(conv0) + fabsf(conv1);
        // Kahan: sum += rowsum
        const float y = __fadd_rn(rowsum, -comp);
        const float t = __fadd_rn(sum, y);
        comp = __fadd_rn(__fadd_rn(t, -sum), -y);
        sum = t;

        // slide row states
        tA0 = tB0; tA1 = tB1; mA0 = mB0; mA1 = mB1;
        tB0 = tC0; tB1 = tC1; mB0 = mC0; mB1 = mC1;
    };

    // main loop: prefetch rows 10..63 (i+10 <= 63 for i < 54 -> no clamp)
    #pragma unroll 8
    for (int i = 0; i < 54; ++i) {
        const float2 c = q[i & 7];
        q[i & 7] = b2[(i + 10) * 32];
        body(c);
    }
    // drain: consume rows 56..63 (stored at i=46..53), no more loads
    #pragma unroll
    for (int i = 54; i < HH - 2; ++i) {
        body(q[i & 7]);
    }

    // lane 31 (cols 62/63) only fed shuffles — drop its contribution
    if (lane == 31) { sum = 0.0f; comp = 0.0f; }

    // fp64 warp shuffle-tree reduction (exact; outside the hot loop)
    double acc = (double)sum - (double)comp;
    #pragma unroll
    for (int off = 16; off > 0; off >>= 1)
        acc += __shfl_xor_sync(FULL, acc, off);
    if (lane == 0) g_scores[plane] = (float)acc;
}

// ---------------------------------------------------------------------------
// Kernel 2: per-batch top-k (k=256) via exact rank counting.
// rank = #(score strictly greater) + #(equal score with lower channel index),
// which reproduces lax.top_k ordering (descending value, ties -> lower index).
// ---------------------------------------------------------------------------
__global__ __launch_bounds__(512) void topk_kernel() {
    __shared__ float s[CH];
    const int b   = blockIdx.x;
    const int tid = threadIdx.x;

    s[tid] = g_scores[b * CH + tid];
    __syncthreads();

    const float my = s[tid];
    int rank = 0;
    #pragma unroll 8
    for (int j = 0; j < CH; ++j) {
        const float v = s[j];
        rank += (v > my) || (v == my && j < tid);
    }
    if (rank < KSEL) g_idx[b * KSEL + rank] = tid;
}

// ---------------------------------------------------------------------------
// Kernel 3: gather selected channel planes.
// R11: 128 threads/block, 8 fully-unrolled INDEPENDENT float4 copies per
// thread (static indices) -> per-thread MLP 8, 2x blocks for wave balance.
// ---------------------------------------------------------------------------
__global__ __launch_bounds__(128) void gather_kernel(const float* __restrict__ x,
                                                     float* __restrict__ out) {
    const int b = blockIdx.y;
    const int r = blockIdx.x;
    const int c = __ldg(&g_idx[b * KSEL + r]);   // broadcast

    const float4* __restrict__ src = reinterpret_cast<const float4*>(x)
                        + ((size_t)(b * CH + c)) * (PLANE / 4);
    float4* __restrict__ dst = reinterpret_cast<float4*>(out)
                  + ((size_t)(b * KSEL + r)) * (PLANE / 4);
    const int tid = threadIdx.x;

    float4 v0 = src[tid + 0 * 128];
    float4 v1 = src[tid + 1 * 128];
    float4 v2 = src[tid + 2 * 128];
    float4 v3 = src[tid + 3 * 128];
    float4 v4 = src[tid + 4 * 128];
    float4 v5 = src[tid + 5 * 128];
    float4 v6 = src[tid + 6 * 128];
    float4 v7 = src[tid + 7 * 128];
    dst[tid + 0 * 128] = v0;
    dst[tid + 1 * 128] = v1;
    dst[tid + 2 * 128] = v2;
    dst[tid + 3 * 128] = v3;
    dst[tid + 4 * 128] = v4;
    dst[tid + 5 * 128] = v5;
    dst[tid + 6 * 128] = v6;
    dst[tid + 7 * 128] = v7;
}

extern "C" void kernel_launch(void* const* d_in, const int* in_sizes, int n_in,
                              void* d_out, int out_size) {
    const float* x = (const float*)d_in[0];
    const float* w = (const float*)d_in[1];
    // Defensive: metadata order should be (x, weight); swap if sizes say otherwise.
    if (n_in >= 2 && in_sizes[0] == 9) {
        const float* t = x; x = w; w = t;
    }
    float* out = (float*)d_out;

    score_kernel<<<(BATCH * CH) / 4, 128>>>(x, w);
    topk_kernel<<<BATCH, 512>>>();
    gather_kernel<<<dim3(KSEL, BATCH), 128>>>(x, out);
}